// round 7
// baseline (speedup 1.0000x reference)
#include <cuda_runtime.h>
#include <cuda_fp16.h>
#include <cstdint>

// ============================================================================
// out[8192,512] = feats @ W^T + bias,  feats[b] = [x (128), x_i*x_j i<=j (8256)]
// K = 8384. FP16x3 (Markidis split) mma.sync GEMM, fused feature gen.
// R7: term-major MMA ordering (no same-acc dependency chains) + pair LUT.
// ============================================================================
static constexpr int DIM    = 128;
static constexpr int NQUAD  = 8256;
static constexpr int NFEAT  = 8384;
static constexpr int BATCH  = 8192;
static constexpr int NOUT   = 512;
static constexpr int KPW    = NFEAT / 2;          // 4192 half2 words per W row

static constexpr int TM = 128;
static constexpr int TN = 256;
static constexpr int TK = 32;                     // 16 half2 words
static constexpr int NKT = NFEAT / TK;            // 262
static constexpr int THREADS = 512;               // 16 warps: 4(M) x 4(N), warp tile 32x64

static constexpr int STRW = 20;                   // words per 16-word row (bank permute)

// SMEM word layout
static constexpr int XT_OFF   = 0;                // fp32 x^T tile, 128 x 132
static constexpr int XT_STRIDE= 132;
static constexpr int AW_OFF   = XT_OFF + DIM * XT_STRIDE;        // 16896
static constexpr int A_COMP   = TM * STRW;                        // 2560
static constexpr int A_STAGE  = 2 * A_COMP;                       // hi+lo
static constexpr int BW_OFF   = AW_OFF + 2 * A_STAGE;             // 27136
static constexpr int B_COMP   = TN * STRW;                        // 5120
static constexpr int B_STAGE  = 2 * B_COMP;
static constexpr int SMEM_WORDS = BW_OFF + 2 * B_STAGE;           // 47616
static constexpr int SMEM_BYTES = SMEM_WORDS * 4;                 // 190464

// ============================================================================
// Device scratch: split weights (half2-packed hi/lo) + pair LUT
// ============================================================================
__device__ __align__(16) uint32_t g_whi[NOUT * KPW];   // 8.58 MB
__device__ __align__(16) uint32_t g_wlo[NOUT * KPW];   // 8.58 MB
__device__ __align__(16) unsigned short g_pairs[NQUAD];

__device__ __forceinline__ uint32_t pack_h2(__half lo16, __half hi16) {
    return (uint32_t)__half_as_ushort(lo16) | ((uint32_t)__half_as_ushort(hi16) << 16);
}
__device__ __forceinline__ void split_f32(float v, __half& h, __half& l) {
    h = __float2half_rn(v);
    l = __float2half_rn(v - __half2float(h));
}
__device__ __forceinline__ int pair_off(int i) { return DIM * i - (i * (i - 1)) / 2; }

// One init kernel: splits W and fills the pair LUT (keeps launch count at 2).
__global__ void init_wsplit_kernel(const float* __restrict__ w) {
    int gidx = blockIdx.x * 256 + threadIdx.x;
    if (gidx < NQUAD) {
        int q = gidx;
        int i = (int)((257.0f - sqrtf(66049.0f - 8.0f * (float)q)) * 0.5f);
        if (i < 0) i = 0;
        if (i > DIM - 1) i = DIM - 1;
        while (i > 0 && pair_off(i) > q) i--;
        while (i < DIM - 1 && pair_off(i + 1) <= q) i++;
        int j = i + (q - pair_off(i));
        g_pairs[q] = (unsigned short)((i << 8) | j);
    }
    int total = NOUT * KPW;
    for (int idx = gidx; idx < total; idx += gridDim.x * 256) {
        float2 v = *reinterpret_cast<const float2*>(w + 2 * (size_t)idx);
        __half h0, l0, h1, l1;
        split_f32(v.x, h0, l0);
        split_f32(v.y, h1, l1);
        g_whi[idx] = pack_h2(h0, h1);
        g_wlo[idx] = pack_h2(l0, l1);
    }
}

// ============================================================================
// helpers
// ============================================================================
__device__ __forceinline__ uint32_t smem_u32(const void* p) {
    uint32_t a;
    asm("{ .reg .u64 t; cvta.to.shared.u64 t, %1; cvt.u32.u64 %0, t; }" : "=r"(a) : "l"(p));
    return a;
}
__device__ __forceinline__ void cp_async16(uint32_t dst, const void* src) {
    asm volatile("cp.async.cg.shared.global [%0], [%1], 16;" :: "r"(dst), "l"(src) : "memory");
}
__device__ __forceinline__ void cp_commit() { asm volatile("cp.async.commit_group;" ::: "memory"); }
template <int N>
__device__ __forceinline__ void cp_wait() { asm volatile("cp.async.wait_group %0;" :: "n"(N) : "memory"); }

__device__ __forceinline__ void ldsm_x4(uint32_t& r0, uint32_t& r1, uint32_t& r2,
                                        uint32_t& r3, uint32_t addr) {
    asm volatile("ldmatrix.sync.aligned.m8n8.x4.shared.b16 {%0,%1,%2,%3}, [%4];"
                 : "=r"(r0), "=r"(r1), "=r"(r2), "=r"(r3) : "r"(addr));
}

__device__ __forceinline__ void mma_f16(float d[4], const uint32_t a[4], const uint32_t b[2]) {
    asm volatile(
        "mma.sync.aligned.m16n8k16.row.col.f32.f16.f16.f32 "
        "{%0,%1,%2,%3}, {%4,%5,%6,%7}, {%8,%9}, {%0,%1,%2,%3};"
        : "+f"(d[0]), "+f"(d[1]), "+f"(d[2]), "+f"(d[3])
        : "r"(a[0]), "r"(a[1]), "r"(a[2]), "r"(a[3]), "r"(b[0]), "r"(b[1]));
}

// ============================================================================
// Fused polynomial-feature GEMM (fp16x3, 16 warps, term-major MMA order)
// ============================================================================
__global__ void __launch_bounds__(THREADS, 1)
poly_gemm_kernel(const float* __restrict__ x,
                 const float* __restrict__ bias,
                 float* __restrict__ out) {
    extern __shared__ float smemf[];
    uint32_t* smemw = reinterpret_cast<uint32_t*>(smemf);
    float* XT = smemf + XT_OFF;
    const uint32_t sb = smem_u32(smemf);

    const int tid  = threadIdx.x;
    const int lane = tid & 31;
    const int warp = tid >> 5;
    const int mw = warp >> 2;           // 0..3  (rows mw*32..)
    const int nw = warp & 3;            // 0..3  (cols nw*64..)

    const int m0 = (int)(blockIdx.x >> 1) * TM;
    const int n0 = (int)(blockIdx.x & 1) * TN;

    // ---------------- XT: transpose x tile ----------------
    for (int idx = tid; idx < TM * DIM; idx += THREADS) {
        int r = idx >> 7, c = idx & 127;
        XT[c * XT_STRIDE + r] = x[(size_t)(m0 + r) * DIM + c];
    }

    // ---------------- B loader: 4 x 16B chunks per thread per tile ----------------
    auto issue_B = [&](int t) {
        uint32_t dst0 = sb + (uint32_t)(BW_OFF + (t & 1) * B_STAGE) * 4u;
        const uint32_t* srch = g_whi + (size_t)n0 * KPW + t * 16;
        const uint32_t* srcl = g_wlo + (size_t)n0 * KPW + t * 16;
#pragma unroll
        for (int i = 0; i < 4; i++) {
            int c   = tid + i * THREADS;        // 0..2047
            int comp= c >> 10;                  // 0 = hi, 1 = lo
            int cc  = c & 1023;
            int row = cc >> 2, qw = cc & 3;     // 256 rows x 4 x 16B
            const uint32_t* src = (comp ? srcl : srch) + (size_t)row * KPW + qw * 4;
            cp_async16(dst0 + (uint32_t)(comp * B_COMP + row * STRW + qw * 4) * 4u, src);
        }
        cp_commit();
    };

    // ---------------- A producer: thread owns k-pair pp, rows r0..r0+3 ----------------
    const int pp = tid & 15;
    const int r0 = (tid >> 4) * 4;      // 32 groups x 4 rows

    auto produce_A = [&](int t) {
        if (t >= NKT) return;
        uint32_t* Ah = smemw + AW_OFF + (t & 1) * A_STAGE + r0 * STRW + pp;
        uint32_t* Al = Ah + A_COMP;
        int kg = t * TK + 2 * pp;
        float v0[4], v1[4];
        if (kg < DIM) {                 // whole tile is linear when t < 4
            float4 a0 = *(const float4*)(XT + (kg + 0) * XT_STRIDE + r0);
            float4 b0 = *(const float4*)(XT + (kg + 1) * XT_STRIDE + r0);
            v0[0]=a0.x; v0[1]=a0.y; v0[2]=a0.z; v0[3]=a0.w;
            v1[0]=b0.x; v1[1]=b0.y; v1[2]=b0.z; v1[3]=b0.w;
        } else {
            int q = kg - DIM;           // even -> 4-byte aligned LUT read
            uint32_t pr = *reinterpret_cast<const uint32_t*>(&g_pairs[q]);
            int i0 = (pr >> 8) & 255, j0 = pr & 255;
            int i1 = (pr >> 24) & 255, j1 = (pr >> 16) & 255;
            float4 xa = *(const float4*)(XT + i0 * XT_STRIDE + r0);
            float4 xb = *(const float4*)(XT + j0 * XT_STRIDE + r0);
            float4 xc = *(const float4*)(XT + i1 * XT_STRIDE + r0);
            float4 xd = *(const float4*)(XT + j1 * XT_STRIDE + r0);
            v0[0]=xa.x*xb.x; v0[1]=xa.y*xb.y; v0[2]=xa.z*xb.z; v0[3]=xa.w*xb.w;
            v1[0]=xc.x*xd.x; v1[1]=xc.y*xd.y; v1[2]=xc.z*xd.z; v1[3]=xc.w*xd.w;
        }
#pragma unroll
        for (int r = 0; r < 4; r++) {
            __half h0, l0, h1, l1;
            split_f32(v0[r], h0, l0);
            split_f32(v1[r], h1, l1);
            Ah[r * STRW] = pack_h2(h0, h1);
            Al[r * STRW] = pack_h2(l0, l1);
        }
    };

    issue_B(0);
    __syncthreads();            // XT ready
    produce_A(0);

    float d[2][8][4];           // [mt][nt][reg]
#pragma unroll
    for (int a = 0; a < 2; a++)
#pragma unroll
        for (int b = 0; b < 8; b++)
#pragma unroll
            for (int c = 0; c < 4; c++) d[a][b][c] = 0.0f;

    // ldmatrix lane-address components (in words)
    const int a_lane_w = (lane & 15) * STRW + (lane >> 4) * 4;
    const int b_lane_w = ((lane & 7) + ((lane >> 4) & 1) * 8) * STRW + ((lane >> 3) & 1) * 4;

    // ---------------- main K loop ----------------
#pragma unroll 1
    for (int t = 0; t < NKT; ++t) {
        cp_wait<0>();
        __syncthreads();                    // A[t], B[t] visible; stage t+1 free
        if (t + 1 < NKT) issue_B(t + 1);
        produce_A(t + 1);

        const uint32_t a_base = sb + (uint32_t)(AW_OFF + (t & 1) * A_STAGE
                                + (mw * 32) * STRW + a_lane_w) * 4u;
        const uint32_t b_base = sb + (uint32_t)(BW_OFF + (t & 1) * B_STAGE
                                + (nw * 64) * STRW + b_lane_w) * 4u;
#pragma unroll
        for (int s = 0; s < 2; s++) {       // two k16 steps per 32-K tile
            uint32_t ahi[2][4], alo[2][4];
#pragma unroll
            for (int mt = 0; mt < 2; mt++) {
                uint32_t ap = a_base + (uint32_t)(mt * 16 * STRW + s * 8) * 4u;
                ldsm_x4(ahi[mt][0], ahi[mt][1], ahi[mt][2], ahi[mt][3], ap);
                ldsm_x4(alo[mt][0], alo[mt][1], alo[mt][2], alo[mt][3],
                        ap + (uint32_t)A_COMP * 4u);
            }
#pragma unroll
            for (int h = 0; h < 2; h++) {   // 4 n-tiles per half (register budget)
                uint32_t bhi[4][2], blo[4][2];
#pragma unroll
                for (int p = 0; p < 2; p++) {   // each ldsm_x4 covers 2 n-tiles
                    uint32_t bp = b_base + (uint32_t)((h * 2 + p) * 16 * STRW + s * 8) * 4u;
                    ldsm_x4(bhi[2*p][0], bhi[2*p][1], bhi[2*p+1][0], bhi[2*p+1][1], bp);
                    ldsm_x4(blo[2*p][0], blo[2*p][1], blo[2*p+1][0], blo[2*p+1][1],
                            bp + (uint32_t)B_COMP * 4u);
                }
                // term-major passes: no back-to-back MMA on the same accumulator
#pragma unroll
                for (int mt = 0; mt < 2; mt++)
#pragma unroll
                    for (int n = 0; n < 4; n++)
                        mma_f16(d[mt][h * 4 + n], ahi[mt], bhi[n]);
#pragma unroll
                for (int mt = 0; mt < 2; mt++)
#pragma unroll
                    for (int n = 0; n < 4; n++)
                        mma_f16(d[mt][h * 4 + n], ahi[mt], blo[n]);
#pragma unroll
                for (int mt = 0; mt < 2; mt++)
#pragma unroll
                    for (int n = 0; n < 4; n++)
                        mma_f16(d[mt][h * 4 + n], alo[mt], bhi[n]);
            }
        }
    }

    // ---------------- epilogue ----------------
    const int g  = lane >> 2;
    const int tg = lane & 3;
#pragma unroll
    for (int mt = 0; mt < 2; mt++) {
        int row = m0 + mw * 32 + mt * 16 + g;
#pragma unroll
        for (int nt = 0; nt < 8; nt++) {
            int col = n0 + nw * 64 + nt * 8 + tg * 2;
            float2 bv = *(const float2*)(bias + col);
            float2 o0 = { d[mt][nt][0] + bv.x, d[mt][nt][1] + bv.y };
            float2 o1 = { d[mt][nt][2] + bv.x, d[mt][nt][3] + bv.y };
            *(float2*)(out + (size_t)row * NOUT + col)       = o0;
            *(float2*)(out + (size_t)(row + 8) * NOUT + col) = o1;
        }
    }
}

// ============================================================================
// Host launch
// ============================================================================
extern "C" void kernel_launch(void* const* d_in, const int* in_sizes, int n_in,
                              void* d_out, int out_size) {
    const float* x    = (const float*)d_in[0];
    const float* w    = (const float*)d_in[1];
    const float* bias = (const float*)d_in[2];
    float* out        = (float*)d_out;

    cudaFuncSetAttribute(poly_gemm_kernel,
                         cudaFuncAttributeMaxDynamicSharedMemorySize, SMEM_BYTES);

    init_wsplit_kernel<<<1184, 256>>>(w);
    poly_gemm_kernel<<<(BATCH / TM) * (NOUT / TN), THREADS, SMEM_BYTES>>>(x, bias, out);
}

// round 8
// speedup vs baseline: 1.1889x; 1.1889x over previous
#include <cuda_runtime.h>
#include <cuda_fp16.h>
#include <cstdint>

// ============================================================================
// out[8192,512] = feats @ W^T + bias,  feats[b] = [x (128), x_i*x_j i<=j (8256)]
// K = 8384. FP16x3 (Markidis split) mma.sync GEMM.
// R8: warp specialization — 16 consumer warps (pure ldsm+mma) + 4 producer
// warps (feature gen + B cp.async), named-barrier producer/consumer sync.
// ============================================================================
static constexpr int DIM    = 128;
static constexpr int NQUAD  = 8256;
static constexpr int NFEAT  = 8384;
static constexpr int BATCH  = 8192;
static constexpr int NOUT   = 512;
static constexpr int KPW    = NFEAT / 2;          // 4192 half2 words per W row

static constexpr int TM = 128;
static constexpr int TN = 256;
static constexpr int TK = 32;                     // 16 half2 words
static constexpr int NKT = NFEAT / TK;            // 262
static constexpr int THREADS = 640;               // 16 consumer + 4 producer warps
static constexpr int NCONS   = 512;               // consumer threads

static constexpr int STRW = 20;                   // words per 16-word row (bank permute)

// SMEM word layout
static constexpr int XT_OFF   = 0;                // fp32 x^T tile, 128 x 132
static constexpr int XT_STRIDE= 132;
static constexpr int AW_OFF   = XT_OFF + DIM * XT_STRIDE;        // 16896
static constexpr int A_COMP   = TM * STRW;                        // 2560
static constexpr int A_STAGE  = 2 * A_COMP;                       // hi+lo
static constexpr int BW_OFF   = AW_OFF + 2 * A_STAGE;             // 27136
static constexpr int B_COMP   = TN * STRW;                        // 5120
static constexpr int B_STAGE  = 2 * B_COMP;
static constexpr int SMEM_WORDS = BW_OFF + 2 * B_STAGE;           // 47616
static constexpr int SMEM_BYTES = SMEM_WORDS * 4;                 // 190464

// Named barriers: full[s] = 1+s, empty[s] = 3+s
#define BAR_SYNC(id)   asm volatile("bar.sync %0, %1;"   :: "r"(id), "r"(THREADS) : "memory")
#define BAR_ARRIVE(id) asm volatile("bar.arrive %0, %1;" :: "r"(id), "r"(THREADS) : "memory")

// ============================================================================
// Device scratch: split weights (half2-packed hi/lo) + pair LUT
// ============================================================================
__device__ __align__(16) uint32_t g_whi[NOUT * KPW];   // 8.58 MB
__device__ __align__(16) uint32_t g_wlo[NOUT * KPW];   // 8.58 MB
__device__ __align__(16) unsigned short g_pairs[NQUAD];

__device__ __forceinline__ uint32_t pack_h2(__half lo16, __half hi16) {
    return (uint32_t)__half_as_ushort(lo16) | ((uint32_t)__half_as_ushort(hi16) << 16);
}
__device__ __forceinline__ void split_f32(float v, __half& h, __half& l) {
    h = __float2half_rn(v);
    l = __float2half_rn(v - __half2float(h));
}
__device__ __forceinline__ int pair_off(int i) { return DIM * i - (i * (i - 1)) / 2; }

__global__ void init_wsplit_kernel(const float* __restrict__ w) {
    int gidx = blockIdx.x * 256 + threadIdx.x;
    if (gidx < NQUAD) {
        int q = gidx;
        int i = (int)((257.0f - sqrtf(66049.0f - 8.0f * (float)q)) * 0.5f);
        if (i < 0) i = 0;
        if (i > DIM - 1) i = DIM - 1;
        while (i > 0 && pair_off(i) > q) i--;
        while (i < DIM - 1 && pair_off(i + 1) <= q) i++;
        int j = i + (q - pair_off(i));
        g_pairs[q] = (unsigned short)((i << 8) | j);
    }
    int total = NOUT * KPW;
    for (int idx = gidx; idx < total; idx += gridDim.x * 256) {
        float2 v = *reinterpret_cast<const float2*>(w + 2 * (size_t)idx);
        __half h0, l0, h1, l1;
        split_f32(v.x, h0, l0);
        split_f32(v.y, h1, l1);
        g_whi[idx] = pack_h2(h0, h1);
        g_wlo[idx] = pack_h2(l0, l1);
    }
}

// ============================================================================
// helpers
// ============================================================================
__device__ __forceinline__ uint32_t smem_u32(const void* p) {
    uint32_t a;
    asm("{ .reg .u64 t; cvta.to.shared.u64 t, %1; cvt.u32.u64 %0, t; }" : "=r"(a) : "l"(p));
    return a;
}
__device__ __forceinline__ void cp_async16(uint32_t dst, const void* src) {
    asm volatile("cp.async.cg.shared.global [%0], [%1], 16;" :: "r"(dst), "l"(src) : "memory");
}
__device__ __forceinline__ void cp_commit() { asm volatile("cp.async.commit_group;" ::: "memory"); }
template <int N>
__device__ __forceinline__ void cp_wait() { asm volatile("cp.async.wait_group %0;" :: "n"(N) : "memory"); }

__device__ __forceinline__ void ldsm_x4(uint32_t& r0, uint32_t& r1, uint32_t& r2,
                                        uint32_t& r3, uint32_t addr) {
    asm volatile("ldmatrix.sync.aligned.m8n8.x4.shared.b16 {%0,%1,%2,%3}, [%4];"
                 : "=r"(r0), "=r"(r1), "=r"(r2), "=r"(r3) : "r"(addr));
}

__device__ __forceinline__ void mma_f16(float d[4], const uint32_t a[4], const uint32_t b[2]) {
    asm volatile(
        "mma.sync.aligned.m16n8k16.row.col.f32.f16.f16.f32 "
        "{%0,%1,%2,%3}, {%4,%5,%6,%7}, {%8,%9}, {%0,%1,%2,%3};"
        : "+f"(d[0]), "+f"(d[1]), "+f"(d[2]), "+f"(d[3])
        : "r"(a[0]), "r"(a[1]), "r"(a[2]), "r"(a[3]), "r"(b[0]), "r"(b[1]));
}

// ============================================================================
// Fused polynomial-feature GEMM (fp16x3, warp-specialized)
// ============================================================================
__global__ void __launch_bounds__(THREADS, 1)
poly_gemm_kernel(const float* __restrict__ x,
                 const float* __restrict__ bias,
                 float* __restrict__ out) {
    extern __shared__ float smemf[];
    uint32_t* smemw = reinterpret_cast<uint32_t*>(smemf);
    float* XT = smemf + XT_OFF;
    const uint32_t sb = smem_u32(smemf);

    const int tid  = threadIdx.x;
    const int lane = tid & 31;
    const int warp = tid >> 5;

    const int m0 = (int)(blockIdx.x >> 1) * TM;
    const int n0 = (int)(blockIdx.x & 1) * TN;

    // ---------------- XT: transpose x tile (all 640 threads) ----------------
    for (int idx = tid; idx < TM * DIM; idx += THREADS) {
        int r = idx >> 7, c = idx & 127;
        XT[c * XT_STRIDE + r] = x[(size_t)(m0 + r) * DIM + c];
    }
    __syncthreads();

    if (warp >= 16) {
        // =================== PRODUCER (4 warps, 128 threads) ===================
        const int pid = tid - NCONS;        // 0..127
        const int pp  = pid & 15;           // k-pair within tile
        const int rb  = (pid >> 4) * 16;    // 16 rows per thread

#pragma unroll 1
        for (int t = 0; t < NKT; ++t) {
            int s = t & 1;
            if (t >= 2) BAR_SYNC(3 + s);    // wait consumers done with buffer s

            // ---- B tile: 16 cp.async16 per thread ----
            {
                uint32_t dst0 = sb + (uint32_t)(BW_OFF + s * B_STAGE) * 4u;
                const uint32_t* srch = g_whi + (size_t)n0 * KPW + t * 16;
                const uint32_t* srcl = g_wlo + (size_t)n0 * KPW + t * 16;
#pragma unroll
                for (int i = 0; i < 16; i++) {
                    int c    = pid + i * 128;      // 0..2047
                    int comp = c >> 10;            // 0 = hi, 1 = lo
                    int cc   = c & 1023;
                    int row  = cc >> 2, qw = cc & 3;
                    const uint32_t* src = (comp ? srcl : srch) + (size_t)row * KPW + qw * 4;
                    cp_async16(dst0 + (uint32_t)(comp * B_COMP + row * STRW + qw * 4) * 4u, src);
                }
                cp_commit();
            }

            // ---- A tile: 2 k-columns x 16 rows per thread ----
            {
                int kg = t * TK + 2 * pp;
                float v0[16], v1[16];
                if (kg < DIM) {
#pragma unroll
                    for (int b = 0; b < 4; b++) {
                        float4 a0 = *(const float4*)(XT + (kg + 0) * XT_STRIDE + rb + 4 * b);
                        float4 b0 = *(const float4*)(XT + (kg + 1) * XT_STRIDE + rb + 4 * b);
                        v0[4*b+0]=a0.x; v0[4*b+1]=a0.y; v0[4*b+2]=a0.z; v0[4*b+3]=a0.w;
                        v1[4*b+0]=b0.x; v1[4*b+1]=b0.y; v1[4*b+2]=b0.z; v1[4*b+3]=b0.w;
                    }
                } else {
                    int q = kg - DIM;   // even -> aligned LUT read
                    uint32_t pr = *reinterpret_cast<const uint32_t*>(&g_pairs[q]);
                    int i0 = (pr >> 8) & 255, j0 = pr & 255;
                    int i1 = (pr >> 24) & 255, j1 = (pr >> 16) & 255;
#pragma unroll
                    for (int b = 0; b < 4; b++) {
                        float4 xa = *(const float4*)(XT + i0 * XT_STRIDE + rb + 4 * b);
                        float4 xb = *(const float4*)(XT + j0 * XT_STRIDE + rb + 4 * b);
                        float4 xc = *(const float4*)(XT + i1 * XT_STRIDE + rb + 4 * b);
                        float4 xd = *(const float4*)(XT + j1 * XT_STRIDE + rb + 4 * b);
                        v0[4*b+0]=xa.x*xb.x; v0[4*b+1]=xa.y*xb.y;
                        v0[4*b+2]=xa.z*xb.z; v0[4*b+3]=xa.w*xb.w;
                        v1[4*b+0]=xc.x*xd.x; v1[4*b+1]=xc.y*xd.y;
                        v1[4*b+2]=xc.z*xd.z; v1[4*b+3]=xc.w*xd.w;
                    }
                }
                uint32_t* Ah = smemw + AW_OFF + s * A_STAGE + rb * STRW + pp;
                uint32_t* Al = Ah + A_COMP;
#pragma unroll
                for (int r = 0; r < 16; r++) {
                    __half h0, l0, h1, l1;
                    split_f32(v0[r], h0, l0);
                    split_f32(v1[r], h1, l1);
                    Ah[r * STRW] = pack_h2(h0, h1);
                    Al[r * STRW] = pack_h2(l0, l1);
                }
            }

            cp_wait<0>();                    // B[s] landed
            BAR_ARRIVE(1 + s);               // publish full[s]
        }
    } else {
        // =================== CONSUMER (16 warps, 512 threads) ===================
        const int mw = warp >> 2;           // 0..3  (rows mw*32..)
        const int nw = warp & 3;            // 0..3  (cols nw*64..)

        float d[2][8][4];
#pragma unroll
        for (int a = 0; a < 2; a++)
#pragma unroll
            for (int b = 0; b < 8; b++)
#pragma unroll
                for (int c = 0; c < 4; c++) d[a][b][c] = 0.0f;

        const int a_lane_w = (lane & 15) * STRW + (lane >> 4) * 4;
        const int b_lane_w = ((lane & 7) + ((lane >> 4) & 1) * 8) * STRW + ((lane >> 3) & 1) * 4;

#pragma unroll 1
        for (int t = 0; t < NKT; ++t) {
            int s = t & 1;
            BAR_SYNC(1 + s);                // wait full[s]

            const uint32_t a_base = sb + (uint32_t)(AW_OFF + s * A_STAGE
                                    + (mw * 32) * STRW + a_lane_w) * 4u;
            const uint32_t b_base = sb + (uint32_t)(BW_OFF + s * B_STAGE
                                    + (nw * 64) * STRW + b_lane_w) * 4u;
#pragma unroll
            for (int ks = 0; ks < 2; ks++) {        // two k16 steps
                uint32_t ahi[2][4], alo[2][4];
#pragma unroll
                for (int mt = 0; mt < 2; mt++) {
                    uint32_t ap = a_base + (uint32_t)(mt * 16 * STRW + ks * 8) * 4u;
                    ldsm_x4(ahi[mt][0], ahi[mt][1], ahi[mt][2], ahi[mt][3], ap);
                    ldsm_x4(alo[mt][0], alo[mt][1], alo[mt][2], alo[mt][3],
                            ap + (uint32_t)A_COMP * 4u);
                }
#pragma unroll
                for (int p = 0; p < 4; p++) {       // 2 n-tiles per batch
                    uint32_t bhi[2][2], blo[2][2];
                    uint32_t bp = b_base + (uint32_t)(p * 16 * STRW + ks * 8) * 4u;
                    ldsm_x4(bhi[0][0], bhi[0][1], bhi[1][0], bhi[1][1], bp);
                    ldsm_x4(blo[0][0], blo[0][1], blo[1][0], blo[1][1],
                            bp + (uint32_t)B_COMP * 4u);
#pragma unroll
                    for (int mt = 0; mt < 2; mt++)
#pragma unroll
                        for (int n = 0; n < 2; n++)
                            mma_f16(d[mt][2*p+n], ahi[mt], bhi[n]);
#pragma unroll
                    for (int mt = 0; mt < 2; mt++)
#pragma unroll
                        for (int n = 0; n < 2; n++)
                            mma_f16(d[mt][2*p+n], ahi[mt], blo[n]);
#pragma unroll
                    for (int mt = 0; mt < 2; mt++)
#pragma unroll
                        for (int n = 0; n < 2; n++)
                            mma_f16(d[mt][2*p+n], alo[mt], bhi[n]);
                }
            }
            BAR_ARRIVE(3 + s);              // publish empty[s]
        }

        // ---------------- epilogue ----------------
        const int g  = lane >> 2;
        const int tg = lane & 3;
#pragma unroll
        for (int mt = 0; mt < 2; mt++) {
            int row = m0 + mw * 32 + mt * 16 + g;
#pragma unroll
            for (int nt = 0; nt < 8; nt++) {
                int col = n0 + nw * 64 + nt * 8 + tg * 2;
                float2 bv = *(const float2*)(bias + col);
                float2 o0 = { d[mt][nt][0] + bv.x, d[mt][nt][1] + bv.y };
                float2 o1 = { d[mt][nt][2] + bv.x, d[mt][nt][3] + bv.y };
                *(float2*)(out + (size_t)row * NOUT + col)       = o0;
                *(float2*)(out + (size_t)(row + 8) * NOUT + col) = o1;
            }
        }
    }
}

// ============================================================================
// Host launch
// ============================================================================
extern "C" void kernel_launch(void* const* d_in, const int* in_sizes, int n_in,
                              void* d_out, int out_size) {
    const float* x    = (const float*)d_in[0];
    const float* w    = (const float*)d_in[1];
    const float* bias = (const float*)d_in[2];
    float* out        = (float*)d_out;

    cudaFuncSetAttribute(poly_gemm_kernel,
                         cudaFuncAttributeMaxDynamicSharedMemorySize, SMEM_BYTES);

    init_wsplit_kernel<<<1184, 256>>>(w);
    poly_gemm_kernel<<<(BATCH / TM) * (NOUT / TN), THREADS, SMEM_BYTES>>>(x, bias, out);
}